// round 16
// baseline (speedup 1.0000x reference)
#include <cuda_runtime.h>
#include <cuda_bf16.h>
#include <math.h>
#include <stdint.h>

#define EMAX 250000
#define NMAX 25000

#define INV_NN   0.51298917604257706f   // 1/sqrt(3.8)
#define INV3     0.57735026918962576f
#define INV112   0.89285714285714285f   // 1/1.12
#define S3       1.7320508075688772f
#define S5       2.2360679774997896f
#define S7       2.6457513110645907f
#define S15      3.8729833462074170f
#define S105     10.246950765959598f
#define C358     2.0916500663351889f
#define C218     1.6201851746019651f
#define RS3      0.57735026918962576f
#define RS5      0.44721359549995794f
#define RS7      0.37796447300922720f
#define SCALE1   (INV3 * 0.5f / 16.0f * INV_NN)
#define SCALE2   (INV3 / 128.0f * INV_NN)

// ---------------------------------------------------------------------------
// Scratch
// ---------------------------------------------------------------------------
__device__ __align__(16) float g_vecS   [EMAX * 4];   // dst-sorted: nx,ny,nz,srcbits
__device__ __align__(16) float g_x      [NMAX * 16];
__device__ __align__(16) float g_basisS [EMAX * 4];   // dst-sorted basis
__device__ __align__(16) float g_basis2S[EMAX * 4];   // src-sorted basis (+dst bits)
__device__ int   g_hist [NMAX];
__device__ int   g_hist2[NMAX];
__device__ int   g_off  [NMAX + 1];
__device__ int   g_off2 [NMAX + 1];
__device__ int   g_r1   [EMAX];
__device__ int   g_r2   [EMAX];
__device__ volatile int g_part[64];
__device__ volatile int g_flag[64];
__device__ __align__(16) uint32_t g_T1 [(size_t)NMAX * 512];
__device__ __align__(16) uint32_t g_T2 [(size_t)NMAX * 512];
__device__ __align__(16) uint4 g_WB  [24576];  // W1b frag hi/lo
__device__ __align__(16) uint4 g_WB2 [4096];   // W2b frag hi/lo
__device__ __align__(16) float g_z   [(size_t)NMAX * 256];

// ---------------------------------------------------------------------------
// helpers
// ---------------------------------------------------------------------------
#define MMA_BF16(d, a0, a1, a2, a3, b0, b1)                                   \
    asm volatile("mma.sync.aligned.m16n8k16.row.col.f32.bf16.bf16.f32 "       \
        "{%0,%1,%2,%3},{%4,%5,%6,%7},{%8,%9},{%0,%1,%2,%3};"                  \
        : "+f"((d)[0]), "+f"((d)[1]), "+f"((d)[2]), "+f"((d)[3])              \
        : "r"(a0), "r"(a1), "r"(a2), "r"(a3), "r"(b0), "r"(b1))

__device__ __forceinline__ uint32_t pack_bf2(float a, float b) {
    __nv_bfloat162 t = __floats2bfloat162_rn(a, b);
    return *(uint32_t*)&t;
}
__device__ __forceinline__ float bf_round(float v) {
    __nv_bfloat16 t = __float2bfloat16_rn(v);
    return __bfloat162float(t);
}

// sh from a normalized direction
__device__ __forceinline__ void sh_eval(float x, float y, float z,
                                        float4& s0, float4& s1,
                                        float4& s2, float4& s3)
{
    float x2 = x * x, y2 = y * y, z2 = z * z;
    s0 = make_float4(1.0f, S3 * x, S3 * y, S3 * z);
    s1 = make_float4(S15 * x * z, S15 * x * y,
                     0.5f * S5 * (2.0f * y2 - x2 - z2), S15 * y * z);
    s2 = make_float4(0.5f * S15 * (z2 - x2),
                     C358 * x * (3.0f * z2 - x2),
                     S105 * x * y * z,
                     C218 * x * (4.0f * y2 - z2 - x2));
    s3 = make_float4(0.5f * S7 * y * (2.0f * y2 - 3.0f * z2 - 3.0f * x2),
                     C218 * z * (4.0f * y2 - z2 - x2),
                     0.5f * S105 * y * (z2 - x2),
                     C358 * z * (z2 - 3.0f * x2));
}

// ---------------------------------------------------------------------------
// K1: histograms (recording ranks) + weight reorders + zero out/flags.
// ---------------------------------------------------------------------------
__global__ void k_histR(const int* __restrict__ edst,
                        const int* __restrict__ esrc, int E, int nbE,
                        const float* __restrict__ W1b,
                        const float* __restrict__ W2b,
                        float* __restrict__ out, int N)
{
    int b = blockIdx.x;
    int tid = threadIdx.x;
    if (b < nbE) {
        int e = b * 256 + tid;
        if (e < N) out[e] = 0.f;
        if (e < 64) { g_flag[e] = 0; g_part[e] = 0; }
        if (e < E) {
            g_r1[e] = atomicAdd(&g_hist[edst[e]], 1);
            g_r2[e] = atomicAdd(&g_hist2[esrc[e]], 1);
        }
        return;
    }
    if (b < nbE + 96) {
        int idx = (b - nbE) * 256 + tid;
        int lane = idx & 31;
        int t = idx >> 5;
        int j = t % 12;
        int t2 = t / 12;
        int n = j * 8 + (lane >> 2);
        int kbase = t2 * 16 + (lane & 3) * 2;
        float v[4], h[4];
        int kks[4] = {kbase, kbase + 1, kbase + 8, kbase + 9};
#pragma unroll
        for (int q = 0; q < 4; q++) {
            int kk = kks[q];
            int c = kk >> 2, p = kk & 3;
            v[q] = W1b[c * 384 + p * 96 + n];
            h[q] = bf_round(v[q]);
        }
        uint4 o;
        o.x = pack_bf2(h[0], h[1]);
        o.y = pack_bf2(h[2], h[3]);
        o.z = pack_bf2(v[0] - h[0], v[1] - h[1]);
        o.w = pack_bf2(v[2] - h[2], v[3] - h[3]);
        g_WB[idx] = o;
        return;
    }
    {
        int idx = (b - nbE - 96) * 256 + tid;
        int lane = idx & 31;
        int t = idx >> 5;
        int ks = t & 3;
        int j  = t >> 2;
        int n = j * 8 + (lane >> 2);
        int k0 = ks * 16 + (lane & 3) * 2;
        float v00 = W2b[n * 64 + k0],     v01 = W2b[n * 64 + k0 + 1];
        float v10 = W2b[n * 64 + k0 + 8], v11 = W2b[n * 64 + k0 + 9];
        float h00 = bf_round(v00), h01 = bf_round(v01);
        float h10 = bf_round(v10), h11 = bf_round(v11);
        uint4 o;
        o.x = pack_bf2(h00, h01);
        o.y = pack_bf2(h10, h11);
        o.z = pack_bf2(v00 - h00, v01 - h01);
        o.w = pack_bf2(v10 - h10, v11 - h11);
        g_WB2[idx] = o;
    }
}

// ---------------------------------------------------------------------------
// K2: single-kernel exclusive scan with decoupled block prefix
// ---------------------------------------------------------------------------
__global__ void __launch_bounds__(1024) k_scan(int E, int N)
{
    int y = blockIdx.y;
    const int* hist = y ? g_hist2 : g_hist;
    int* off = y ? g_off2 : g_off;
    int b = blockIdx.x, t = threadIdx.x;
    int lane = t & 31, wid = t >> 5;
    int idx = b * 1024 + t;
    int v = (idx < N) ? hist[idx] : 0;
    int xv = v;
#pragma unroll
    for (int o = 1; o < 32; o <<= 1) {
        int tt = __shfl_up_sync(0xffffffffu, xv, o);
        if (lane >= o) xv += tt;
    }
    __shared__ int wsum[32];
    __shared__ int wpre[32];
    __shared__ int spre;
    if (lane == 31) wsum[wid] = xv;
    __syncthreads();
    if (wid == 0) {
        int wv = wsum[lane];
        int xs = wv;
#pragma unroll
        for (int o = 1; o < 32; o <<= 1) {
            int tt = __shfl_up_sync(0xffffffffu, xs, o);
            if (lane >= o) xs += tt;
        }
        wpre[lane] = xs - wv;
    }
    __syncthreads();
    int incl = xv + wpre[wid];
    if (t == 1023) {
        g_part[y * 32 + b] = incl;
        __threadfence();
        g_flag[y * 32 + b] = 1;
    }
    if (wid == 1) {
        int pv = 0;
        if (lane < b) {
            while (g_flag[y * 32 + lane] == 0) { }
            pv = g_part[y * 32 + lane];
        }
#pragma unroll
        for (int o = 16; o > 0; o >>= 1)
            pv += __shfl_down_sync(0xffffffffu, pv, o);
        if (lane == 0) spre = pv;
    }
    __syncthreads();
    int val = incl - v + spre;
    if (idx < N) off[idx] = val;
    if (idx == N) off[N] = E;
}

// ---------------------------------------------------------------------------
// K3: fused sort (no atomics) + re-zero hist arrays for the next replay
// ---------------------------------------------------------------------------
__global__ void k_sort(const int*   __restrict__ edst,
                       const int*   __restrict__ esrc,
                       const float* __restrict__ edge_len,
                       const float* __restrict__ edge_vec, int E, int N)
{
    int e = blockIdx.x * blockDim.x + threadIdx.x;
    if (e < N) { g_hist[e] = 0; g_hist2[e] = 0; }   // last reader was k_scan
    if (e >= E) return;
    int d = edst[e], s = esrc[e];
    int pos  = g_off [d] + g_r1[e];
    int pos2 = g_off2[s] + g_r2[e];

    float len = edge_len[e];
    float t0 = len * 0.5f;
    float t1 = (len - 2.0f) * 0.5f;
    float t2 = (len - 4.0f) * 0.5f;
    float b0 = expf(-t0 * t0) * INV112;
    float b1 = expf(-t1 * t1) * INV112;
    float b2 = expf(-t2 * t2) * INV112;
    *(float4*)&g_basisS [(size_t)pos  * 4] = make_float4(b0, b1, b2, 0.f);
    *(float4*)&g_basis2S[(size_t)pos2 * 4] =
        make_float4(b0, b1, b2, __int_as_float(d));

    float x = edge_vec[e * 3 + 0];
    float y = edge_vec[e * 3 + 1];
    float z = edge_vec[e * 3 + 2];
    float inv = 1.0f / (sqrtf(x * x + y * y + z * z) + 1e-12f);
    *(float4*)&g_vecS[(size_t)pos * 4] =
        make_float4(x * inv, y * inv, z * inv, __int_as_float(s));
}

// ---------------------------------------------------------------------------
// K4: x[n,:] = sum of sh over the node's dst-sorted edges (8 lanes/node)
// ---------------------------------------------------------------------------
__global__ void __launch_bounds__(256) k_x(int N)
{
    int n = blockIdx.x * 32 + (threadIdx.x >> 3);
    int sl = threadIdx.x & 7;
    if (n >= N) return;
    int beg = g_off[n], end = g_off[n + 1];

    float4 a0 = make_float4(0, 0, 0, 0), a1 = a0, a2 = a0, a3 = a0;
    for (int i = beg + sl; i < end; i += 8) {
        float4 v = *(const float4*)&g_vecS[(size_t)i * 4];
        float4 s0, s1, s2, s3;
        sh_eval(v.x, v.y, v.z, s0, s1, s2, s3);
        a0.x += s0.x; a0.y += s0.y; a0.z += s0.z; a0.w += s0.w;
        a1.x += s1.x; a1.y += s1.y; a1.z += s1.z; a1.w += s1.w;
        a2.x += s2.x; a2.y += s2.y; a2.z += s2.z; a2.w += s2.w;
        a3.x += s3.x; a3.y += s3.y; a3.z += s3.z; a3.w += s3.w;
    }
#pragma unroll
    for (int o = 4; o > 0; o >>= 1) {
        a0.x += __shfl_down_sync(0xffffffffu, a0.x, o, 8);
        a0.y += __shfl_down_sync(0xffffffffu, a0.y, o, 8);
        a0.z += __shfl_down_sync(0xffffffffu, a0.z, o, 8);
        a0.w += __shfl_down_sync(0xffffffffu, a0.w, o, 8);
        a1.x += __shfl_down_sync(0xffffffffu, a1.x, o, 8);
        a1.y += __shfl_down_sync(0xffffffffu, a1.y, o, 8);
        a1.z += __shfl_down_sync(0xffffffffu, a1.z, o, 8);
        a1.w += __shfl_down_sync(0xffffffffu, a1.w, o, 8);
        a2.x += __shfl_down_sync(0xffffffffu, a2.x, o, 8);
        a2.y += __shfl_down_sync(0xffffffffu, a2.y, o, 8);
        a2.z += __shfl_down_sync(0xffffffffu, a2.z, o, 8);
        a2.w += __shfl_down_sync(0xffffffffu, a2.w, o, 8);
        a3.x += __shfl_down_sync(0xffffffffu, a3.x, o, 8);
        a3.y += __shfl_down_sync(0xffffffffu, a3.y, o, 8);
        a3.z += __shfl_down_sync(0xffffffffu, a3.z, o, 8);
        a3.w += __shfl_down_sync(0xffffffffu, a3.w, o, 8);
    }
    if (sl == 0) {
        float4* xp = (float4*)&g_x[(size_t)n * 16];
        xp[0] = a0; xp[1] = a1; xp[2] = a2; xp[3] = a3;
    }
}

// ---------------------------------------------------------------------------
// K5: build T with fused dots (R13 proven version)
// ---------------------------------------------------------------------------
__global__ void __launch_bounds__(256) k_buildT(const float* __restrict__ W1a, int N)
{
    __shared__ float sW[768];
    for (int i = threadIdx.x; i < 768; i += 256) sW[i] = W1a[i];
    __syncthreads();

    int w = blockIdx.x * 8 + (threadIdx.x >> 5);
    int lane = threadIdx.x & 31;
    if (w >= N) return;
    int beg = g_off[w], end = g_off[w + 1];

    float wa0[8], wa1[8], wa2[8];
#pragma unroll
    for (int j = 0; j < 8; j++) {
        int c = j * 32 + lane;
        wa0[j] = sW[c]; wa1[j] = sW[256 + c]; wa2[j] = sW[512 + c];
    }
    float4 acc[8];
#pragma unroll
    for (int j = 0; j < 8; j++) acc[j] = make_float4(0.f, 0.f, 0.f, 0.f);

    for (int chunk = beg; chunk < end; chunk += 32) {
        int cnt = min(32, end - chunk);

        float4 dt = make_float4(0.f, 0.f, 0.f, 0.f);
        float4 bs = make_float4(0.f, 0.f, 0.f, 0.f);
        if (lane < cnt) {
            float4 v = *(const float4*)&g_vecS[(size_t)(chunk + lane) * 4];
            int src = __float_as_int(v.w);
            float4 s0, s1, s2, s3;
            sh_eval(v.x, v.y, v.z, s0, s1, s2, s3);
            const float4* xp = (const float4*)&g_x[(size_t)src * 16];
            float4 x0 = xp[0], x1 = xp[1], x2 = xp[2], x3 = xp[3];
            float d0 = x0.x * s0.x;
            float d1 = (x0.y * s0.y + x0.z * s0.z + x0.w * s0.w) * RS3;
            float d2 = (x1.x * s1.x + x1.y * s1.y + x1.z * s1.z +
                        x1.w * s1.w + x2.x * s2.x) * RS5;
            float d3 = (x2.y * s2.y + x2.z * s2.z + x2.w * s2.w +
                        x3.x * s3.x + x3.y * s3.y + x3.z * s3.z +
                        x3.w * s3.w) * RS7;
            dt = make_float4(d0 * INV_NN, d1 * INV_NN, d2 * INV_NN, d3 * INV_NN);
            bs = *(const float4*)&g_basisS[(size_t)(chunk + lane) * 4];
        }

        for (int j = 0; j < cnt; j++) {
            float dtx = __shfl_sync(0xffffffffu, dt.x, j);
            float dty = __shfl_sync(0xffffffffu, dt.y, j);
            float dtz = __shfl_sync(0xffffffffu, dt.z, j);
            float dtw = __shfl_sync(0xffffffffu, dt.w, j);
            float bsx = __shfl_sync(0xffffffffu, bs.x, j);
            float bsy = __shfl_sync(0xffffffffu, bs.y, j);
            float bsz = __shfl_sync(0xffffffffu, bs.z, j);
#pragma unroll
            for (int q = 0; q < 8; q++) {
                float h1 = fmaxf(fmaf(bsx, wa0[q],
                                 fmaf(bsy, wa1[q], bsz * wa2[q])), 0.f);
                acc[q].x = fmaf(h1, dtx, acc[q].x);
                acc[q].y = fmaf(h1, dty, acc[q].y);
                acc[q].z = fmaf(h1, dtz, acc[q].z);
                acc[q].w = fmaf(h1, dtw, acc[q].w);
            }
        }
    }

    uint32_t* t1 = &g_T1[(size_t)w * 512];
    uint32_t* t2 = &g_T2[(size_t)w * 512];
#pragma unroll
    for (int j = 0; j < 8; j++) {
        int idx = j * 32 + lane;
        float4 vv = acc[j];
        float hx = bf_round(vv.x), hy = bf_round(vv.y);
        float hz = bf_round(vv.z), hw = bf_round(vv.w);
        uint2 w1 = make_uint2(pack_bf2(hx, hy), pack_bf2(hz, hw));
        uint2 w2 = make_uint2(pack_bf2(vv.x - hx, vv.y - hy),
                              pack_bf2(vv.z - hz, vv.w - hw));
        *(uint2*)&t1[idx * 2] = w1;
        *(uint2*)&t2[idx * 2] = w2;
    }
}

// ---------------------------------------------------------------------------
// K6: fused GEMM1 (h) -> activation (y) -> GEMM2 (z, f32 out)  [R13 proven]
// ---------------------------------------------------------------------------
#define ASTR 20

__global__ void __launch_bounds__(128) k_gemm_fused(int M)
{
    __shared__ uint32_t A1s[64 * ASTR];
    __shared__ uint32_t A2s[64 * ASTR];
    __shared__ uint4    Bs[768];
    __shared__ uint32_t Y1[64 * 36];
    __shared__ uint32_t Y2[64 * 36];

    int tid = threadIdx.x, wid = tid >> 5, lane = tid & 31;
    int m0 = blockIdx.x * 64;

    float acc[12][4];
#pragma unroll
    for (int j = 0; j < 12; j++)
#pragma unroll
        for (int q = 0; q < 4; q++) acc[j][q] = 0.f;

    uint4 a1R[2], a2R[2], bR[6];
    const uint4 zero4 = make_uint4(0u, 0u, 0u, 0u);

#pragma unroll
    for (int it = 0; it < 2; it++) {
        int idx = tid + 128 * it;
        int r = idx >> 2, qc = idx & 3;
        int gm = m0 + r;
        if (gm < M) {
            a1R[it] = *(const uint4*)&g_T1[(size_t)gm * 512 + qc * 4];
            a2R[it] = *(const uint4*)&g_T2[(size_t)gm * 512 + qc * 4];
        } else { a1R[it] = zero4; a2R[it] = zero4; }
    }
#pragma unroll
    for (int it = 0; it < 6; it++)
        bR[it] = g_WB[tid + 128 * it];

    for (int kc = 0; kc < 32; kc++) {
        __syncthreads();
#pragma unroll
        for (int it = 0; it < 2; it++) {
            int idx = tid + 128 * it;
            int r = idx >> 2, qc = idx & 3;
            *(uint4*)&A1s[r * ASTR + qc * 4] = a1R[it];
            *(uint4*)&A2s[r * ASTR + qc * 4] = a2R[it];
        }
#pragma unroll
        for (int it = 0; it < 6; it++)
            Bs[tid + 128 * it] = bR[it];
        __syncthreads();

        if (kc < 31) {
            int kn = kc + 1;
#pragma unroll
            for (int it = 0; it < 2; it++) {
                int idx = tid + 128 * it;
                int r = idx >> 2, qc = idx & 3;
                int gm = m0 + r;
                if (gm < M) {
                    a1R[it] = *(const uint4*)&g_T1[(size_t)gm * 512 + kn * 16 + qc * 4];
                    a2R[it] = *(const uint4*)&g_T2[(size_t)gm * 512 + kn * 16 + qc * 4];
                } else { a1R[it] = zero4; a2R[it] = zero4; }
            }
#pragma unroll
            for (int it = 0; it < 6; it++)
                bR[it] = g_WB[kn * 768 + tid + 128 * it];
        }

#pragma unroll
        for (int ks = 0; ks < 2; ks++) {
            int ar = (wid * 16 + (lane >> 2)) * ASTR + ks * 8 + (lane & 3);
            uint32_t a10 = A1s[ar];
            uint32_t a11 = A1s[ar + 8 * ASTR];
            uint32_t a12 = A1s[ar + 4];
            uint32_t a13 = A1s[ar + 8 * ASTR + 4];
            uint32_t a20 = A2s[ar];
            uint32_t a21 = A2s[ar + 8 * ASTR];
            uint32_t a22 = A2s[ar + 4];
            uint32_t a23 = A2s[ar + 8 * ASTR + 4];
#pragma unroll
            for (int j = 0; j < 12; j++) {
                uint4 b = Bs[(ks * 12 + j) * 32 + lane];
                MMA_BF16(acc[j], a10, a11, a12, a13, b.x, b.y);
                MMA_BF16(acc[j], a10, a11, a12, a13, b.z, b.w);
                MMA_BF16(acc[j], a20, a21, a22, a23, b.x, b.y);
            }
        }
    }

    // ---- activation: h fragments -> y, bf16-split into Y1/Y2 smem
    int r0 = wid * 16 + (lane >> 2);
#pragma unroll
    for (int half = 0; half < 2; half++) {
        int row = r0 + half * 8;
#pragma unroll
        for (int j = 0; j < 8; j++) {
            float v0, v1;
            if (j < 4) {
                float s0 = acc[j][half * 2] * SCALE1;
                float s1 = acc[j][half * 2 + 1] * SCALE1;
                if (j < 2) { v0 = fmaxf(s0, 0.f); v1 = fmaxf(s1, 0.f); }
                else       { v0 = fabsf(s0);      v1 = fabsf(s1); }
            } else {
                float g0 = acc[j][half * 2] * SCALE1;
                float g1 = acc[j][half * 2 + 1] * SCALE1;
                float q0 = acc[j + 4][half * 2] * SCALE1;
                float q1 = acc[j + 4][half * 2 + 1] * SCALE1;
                float a0, a1;
                if ((j & 1) == 0) { a0 = fmaxf(g0, 0.f); a1 = fmaxf(g1, 0.f); }
                else              { a0 = tanhf(g0);      a1 = tanhf(g1); }
                v0 = a0 * q0; v1 = a1 * q1;
            }
            float h0 = bf_round(v0), h1 = bf_round(v1);
            int widx = row * 36 + j * 4 + (lane & 3);
            Y1[widx] = pack_bf2(h0, h1);
            Y2[widx] = pack_bf2(v0 - h0, v1 - h1);
        }
    }
    __syncthreads();

    // ---- GEMM2: z = y @ W2b^T (K=64, N=256), f32 output
#pragma unroll
    for (int nh = 0; nh < 2; nh++) {
        float zac[16][4];
#pragma unroll
        for (int j = 0; j < 16; j++)
#pragma unroll
            for (int q = 0; q < 4; q++) zac[j][q] = 0.f;

#pragma unroll
        for (int ks = 0; ks < 4; ks++) {
            int aw = (wid * 16 + (lane >> 2)) * 36 + ks * 8 + (lane & 3);
            uint32_t a10 = Y1[aw];
            uint32_t a11 = Y1[aw + 8 * 36];
            uint32_t a12 = Y1[aw + 4];
            uint32_t a13 = Y1[aw + 8 * 36 + 4];
            uint32_t a20 = Y2[aw];
            uint32_t a21 = Y2[aw + 8 * 36];
            uint32_t a22 = Y2[aw + 4];
            uint32_t a23 = Y2[aw + 8 * 36 + 4];
#pragma unroll
            for (int j = 0; j < 16; j++) {
                uint4 b = g_WB2[((nh * 16 + j) * 4 + ks) * 32 + lane];
                MMA_BF16(zac[j], a10, a11, a12, a13, b.x, b.y);
                MMA_BF16(zac[j], a10, a11, a12, a13, b.z, b.w);
                MMA_BF16(zac[j], a20, a21, a22, a23, b.x, b.y);
            }
        }
        int rr = lane >> 2, c2 = (lane & 3) * 2;
        int gm0 = m0 + wid * 16 + rr;
#pragma unroll
        for (int j = 0; j < 16; j++) {
            int col = nh * 128 + j * 8 + c2;
            if (gm0 < M)
                *(float2*)&g_z[(size_t)gm0 * 256 + col] =
                    make_float2(zac[j][0], zac[j][1]);
            if (gm0 + 8 < M)
                *(float2*)&g_z[(size_t)(gm0 + 8) * 256 + col] =
                    make_float2(zac[j][2], zac[j][3]);
        }
    }
}

// ---------------------------------------------------------------------------
// K7: final pass, warp per SRC node; 4-edge batched independent reductions
// ---------------------------------------------------------------------------
__global__ void __launch_bounds__(256) k_final(const float* __restrict__ W2a,
                                               float* __restrict__ out, int N)
{
    __shared__ float sW[768];
    for (int i = threadIdx.x; i < 768; i += 256) sW[i] = W2a[i];
    __syncthreads();

    int w = blockIdx.x * 8 + (threadIdx.x >> 5);
    int lane = threadIdx.x & 31;
    if (w >= N) return;
    int beg = g_off2[w], end = g_off2[w + 1];
    if (beg == end) return;

    float w0[8], w1[8], w2[8], zr[8];
    const float* zp = &g_z[(size_t)w * 256];
#pragma unroll
    for (int j = 0; j < 8; j++) {
        int c = j * 32 + lane;
        w0[j] = sW[c]; w1[j] = sW[256 + c]; w2[j] = sW[512 + c];
        zr[j] = zp[c];
    }

    for (int i = beg; i < end; i += 4) {
        int nb = end - i; if (nb > 4) nb = 4;
        float4 bsv[4];
        float sum[4];
#pragma unroll
        for (int q = 0; q < 4; q++) sum[q] = 0.f;
#pragma unroll
        for (int q = 0; q < 4; q++)
            bsv[q] = (q < nb) ? *(const float4*)&g_basis2S[(size_t)(i + q) * 4]
                              : make_float4(0.f, 0.f, 0.f, 0.f);
#pragma unroll
        for (int j = 0; j < 8; j++) {
#pragma unroll
            for (int q = 0; q < 4; q++) {
                float h2 = fmaxf(fmaf(bsv[q].x, w0[j],
                                 fmaf(bsv[q].y, w1[j], bsv[q].z * w2[j])), 0.f);
                sum[q] = fmaf(h2, zr[j], sum[q]);
            }
        }
        // 4 independent butterfly reductions, interleaved (pipelined SHFLs)
#pragma unroll
        for (int o = 16; o > 0; o >>= 1) {
            sum[0] += __shfl_down_sync(0xffffffffu, sum[0], o);
            sum[1] += __shfl_down_sync(0xffffffffu, sum[1], o);
            sum[2] += __shfl_down_sync(0xffffffffu, sum[2], o);
            sum[3] += __shfl_down_sync(0xffffffffu, sum[3], o);
        }
        if (lane == 0) {
#pragma unroll
            for (int q = 0; q < 4; q++) {
                if (q < nb) {
                    int dst = __float_as_int(bsv[q].w);
                    atomicAdd(&out[dst], sum[q] * SCALE2);
                }
            }
        }
    }
}

// ---------------------------------------------------------------------------
// Launch
// ---------------------------------------------------------------------------
extern "C" void kernel_launch(void* const* d_in, const int* in_sizes, int n_in,
                              void* d_out, int out_size)
{
    const float* edge_vec = (const float*)d_in[0];
    const float* edge_len = (const float*)d_in[1];
    const float* W1a      = (const float*)d_in[2];
    const float* W1b      = (const float*)d_in[3];
    const float* W2a      = (const float*)d_in[4];
    const float* W2b      = (const float*)d_in[5];
    const int*   esrc     = (const int*)d_in[6];
    const int*   edst     = (const int*)d_in[7];
    float* out = (float*)d_out;

    int E = in_sizes[1];
    int N = out_size;
    if (E > EMAX) E = EMAX;
    if (N > NMAX) N = NMAX;

    int nbE = (E + 255) / 256;
    int nbScan = (N + 1023) / 1024;   // 25

    k_histR<<<nbE + 96 + 16, 256>>>(edst, esrc, E, nbE, W1b, W2b, out, N);
    k_scan <<<dim3(nbScan, 2), 1024>>>(E, N);
    k_sort <<<nbE, 256>>>(edst, esrc, edge_len, edge_vec, E, N);
    k_x    <<<(N + 31) / 32, 256>>>(N);
    k_buildT<<<(N + 7) / 8, 256>>>(W1a, N);
    k_gemm_fused<<<(N + 63) / 64, 128>>>(N);
    k_final<<<(N + 7) / 8, 256>>>(W2a, out, N);
}

// round 17
// speedup vs baseline: 1.0383x; 1.0383x over previous
#include <cuda_runtime.h>
#include <cuda_bf16.h>
#include <math.h>
#include <stdint.h>

#define EMAX 250000
#define NMAX 25000

#define INV_NN   0.51298917604257706f   // 1/sqrt(3.8)
#define INV3     0.57735026918962576f
#define INV112   0.89285714285714285f   // 1/1.12
#define S3       1.7320508075688772f
#define S5       2.2360679774997896f
#define S7       2.6457513110645907f
#define S15      3.8729833462074170f
#define S105     10.246950765959598f
#define C358     2.0916500663351889f
#define C218     1.6201851746019651f
#define RS3      0.57735026918962576f
#define RS5      0.44721359549995794f
#define RS7      0.37796447300922720f
#define SCALE1   (INV3 * 0.5f / 16.0f * INV_NN)
#define SCALE2   (INV3 / 128.0f * INV_NN)

// ---------------------------------------------------------------------------
// Scratch
// ---------------------------------------------------------------------------
// interleaved per-edge record (dst-sorted): [nx,ny,nz,srcbits, b0,b1,b2,pad]
__device__ __align__(32) float g_vbS    [(size_t)EMAX * 8];
__device__ __align__(16) float g_x      [NMAX * 16];
__device__ __align__(16) float g_basis2S[EMAX * 4];   // src-sorted basis (+dst bits)
__device__ int   g_hist [NMAX];
__device__ int   g_hist2[NMAX];
__device__ int   g_off  [NMAX + 1];
__device__ int   g_off2 [NMAX + 1];
__device__ int   g_r1   [EMAX];
__device__ int   g_r2   [EMAX];
__device__ volatile int g_part[64];
__device__ volatile int g_flag[64];
__device__ __align__(16) uint32_t g_T1 [(size_t)NMAX * 512];
__device__ __align__(16) uint32_t g_T2 [(size_t)NMAX * 512];
__device__ __align__(16) uint4 g_WB  [24576];  // W1b frag hi/lo
__device__ __align__(16) uint4 g_WB2 [4096];   // W2b frag hi/lo
__device__ __align__(16) float g_z   [(size_t)NMAX * 256];

// ---------------------------------------------------------------------------
// helpers
// ---------------------------------------------------------------------------
#define MMA_BF16(d, a0, a1, a2, a3, b0, b1)                                   \
    asm volatile("mma.sync.aligned.m16n8k16.row.col.f32.bf16.bf16.f32 "       \
        "{%0,%1,%2,%3},{%4,%5,%6,%7},{%8,%9},{%0,%1,%2,%3};"                  \
        : "+f"((d)[0]), "+f"((d)[1]), "+f"((d)[2]), "+f"((d)[3])              \
        : "r"(a0), "r"(a1), "r"(a2), "r"(a3), "r"(b0), "r"(b1))

__device__ __forceinline__ uint32_t pack_bf2(float a, float b) {
    __nv_bfloat162 t = __floats2bfloat162_rn(a, b);
    return *(uint32_t*)&t;
}
__device__ __forceinline__ float bf_round(float v) {
    __nv_bfloat16 t = __float2bfloat16_rn(v);
    return __bfloat162float(t);
}

// sh from a normalized direction
__device__ __forceinline__ void sh_eval(float x, float y, float z,
                                        float4& s0, float4& s1,
                                        float4& s2, float4& s3)
{
    float x2 = x * x, y2 = y * y, z2 = z * z;
    s0 = make_float4(1.0f, S3 * x, S3 * y, S3 * z);
    s1 = make_float4(S15 * x * z, S15 * x * y,
                     0.5f * S5 * (2.0f * y2 - x2 - z2), S15 * y * z);
    s2 = make_float4(0.5f * S15 * (z2 - x2),
                     C358 * x * (3.0f * z2 - x2),
                     S105 * x * y * z,
                     C218 * x * (4.0f * y2 - z2 - x2));
    s3 = make_float4(0.5f * S7 * y * (2.0f * y2 - 3.0f * z2 - 3.0f * x2),
                     C218 * z * (4.0f * y2 - z2 - x2),
                     0.5f * S105 * y * (z2 - x2),
                     C358 * z * (z2 - 3.0f * x2));
}

// ---------------------------------------------------------------------------
// K1: histograms (recording ranks) + weight reorders + zero out/flags.
// ---------------------------------------------------------------------------
__global__ void k_histR(const int* __restrict__ edst,
                        const int* __restrict__ esrc, int E, int nbE,
                        const float* __restrict__ W1b,
                        const float* __restrict__ W2b,
                        float* __restrict__ out, int N)
{
    int b = blockIdx.x;
    int tid = threadIdx.x;
    if (b < nbE) {
        int e = b * 256 + tid;
        if (e < N) out[e] = 0.f;
        if (e < 64) { g_flag[e] = 0; g_part[e] = 0; }
        if (e < E) {
            g_r1[e] = atomicAdd(&g_hist[edst[e]], 1);
            g_r2[e] = atomicAdd(&g_hist2[esrc[e]], 1);
        }
        return;
    }
    if (b < nbE + 96) {
        int idx = (b - nbE) * 256 + tid;
        int lane = idx & 31;
        int t = idx >> 5;
        int j = t % 12;
        int t2 = t / 12;
        int n = j * 8 + (lane >> 2);
        int kbase = t2 * 16 + (lane & 3) * 2;
        float v[4], h[4];
        int kks[4] = {kbase, kbase + 1, kbase + 8, kbase + 9};
#pragma unroll
        for (int q = 0; q < 4; q++) {
            int kk = kks[q];
            int c = kk >> 2, p = kk & 3;
            v[q] = W1b[c * 384 + p * 96 + n];
            h[q] = bf_round(v[q]);
        }
        uint4 o;
        o.x = pack_bf2(h[0], h[1]);
        o.y = pack_bf2(h[2], h[3]);
        o.z = pack_bf2(v[0] - h[0], v[1] - h[1]);
        o.w = pack_bf2(v[2] - h[2], v[3] - h[3]);
        g_WB[idx] = o;
        return;
    }
    {
        int idx = (b - nbE - 96) * 256 + tid;
        int lane = idx & 31;
        int t = idx >> 5;
        int ks = t & 3;
        int j  = t >> 2;
        int n = j * 8 + (lane >> 2);
        int k0 = ks * 16 + (lane & 3) * 2;
        float v00 = W2b[n * 64 + k0],     v01 = W2b[n * 64 + k0 + 1];
        float v10 = W2b[n * 64 + k0 + 8], v11 = W2b[n * 64 + k0 + 9];
        float h00 = bf_round(v00), h01 = bf_round(v01);
        float h10 = bf_round(v10), h11 = bf_round(v11);
        uint4 o;
        o.x = pack_bf2(h00, h01);
        o.y = pack_bf2(h10, h11);
        o.z = pack_bf2(v00 - h00, v01 - h01);
        o.w = pack_bf2(v10 - h10, v11 - h11);
        g_WB2[idx] = o;
    }
}

// ---------------------------------------------------------------------------
// K2: single-kernel exclusive scan with decoupled block prefix
// ---------------------------------------------------------------------------
__global__ void __launch_bounds__(1024) k_scan(int E, int N)
{
    int y = blockIdx.y;
    const int* hist = y ? g_hist2 : g_hist;
    int* off = y ? g_off2 : g_off;
    int b = blockIdx.x, t = threadIdx.x;
    int lane = t & 31, wid = t >> 5;
    int idx = b * 1024 + t;
    int v = (idx < N) ? hist[idx] : 0;
    int xv = v;
#pragma unroll
    for (int o = 1; o < 32; o <<= 1) {
        int tt = __shfl_up_sync(0xffffffffu, xv, o);
        if (lane >= o) xv += tt;
    }
    __shared__ int wsum[32];
    __shared__ int wpre[32];
    __shared__ int spre;
    if (lane == 31) wsum[wid] = xv;
    __syncthreads();
    if (wid == 0) {
        int wv = wsum[lane];
        int xs = wv;
#pragma unroll
        for (int o = 1; o < 32; o <<= 1) {
            int tt = __shfl_up_sync(0xffffffffu, xs, o);
            if (lane >= o) xs += tt;
        }
        wpre[lane] = xs - wv;
    }
    __syncthreads();
    int incl = xv + wpre[wid];
    if (t == 1023) {
        g_part[y * 32 + b] = incl;
        __threadfence();
        g_flag[y * 32 + b] = 1;
    }
    if (wid == 1) {
        int pv = 0;
        if (lane < b) {
            while (g_flag[y * 32 + lane] == 0) { }
            pv = g_part[y * 32 + lane];
        }
#pragma unroll
        for (int o = 16; o > 0; o >>= 1)
            pv += __shfl_down_sync(0xffffffffu, pv, o);
        if (lane == 0) spre = pv;
    }
    __syncthreads();
    int val = incl - v + spre;
    if (idx < N) off[idx] = val;
    if (idx == N) off[N] = E;
}

// ---------------------------------------------------------------------------
// K3: fused sort (no atomics); vec+basis in ONE 32B record per edge
// ---------------------------------------------------------------------------
__global__ void k_sort(const int*   __restrict__ edst,
                       const int*   __restrict__ esrc,
                       const float* __restrict__ edge_len,
                       const float* __restrict__ edge_vec, int E, int N)
{
    int e = blockIdx.x * blockDim.x + threadIdx.x;
    if (e < N) { g_hist[e] = 0; g_hist2[e] = 0; }   // last reader was k_scan
    if (e >= E) return;
    int d = edst[e], s = esrc[e];
    int pos  = g_off [d] + g_r1[e];
    int pos2 = g_off2[s] + g_r2[e];

    float len = edge_len[e];
    float t0 = len * 0.5f;
    float t1 = (len - 2.0f) * 0.5f;
    float t2 = (len - 4.0f) * 0.5f;
    float b0 = expf(-t0 * t0) * INV112;
    float b1 = expf(-t1 * t1) * INV112;
    float b2 = expf(-t2 * t2) * INV112;

    float x = edge_vec[e * 3 + 0];
    float y = edge_vec[e * 3 + 1];
    float z = edge_vec[e * 3 + 2];
    float inv = 1.0f / (sqrtf(x * x + y * y + z * z) + 1e-12f);

    float* rec = &g_vbS[(size_t)pos * 8];
    *(float4*)rec       = make_float4(x * inv, y * inv, z * inv,
                                      __int_as_float(s));
    *(float4*)(rec + 4) = make_float4(b0, b1, b2, 0.f);

    *(float4*)&g_basis2S[(size_t)pos2 * 4] =
        make_float4(b0, b1, b2, __int_as_float(d));
}

// ---------------------------------------------------------------------------
// K4: x[n,:] = sum of sh over the node's dst-sorted edges (8 lanes/node)
// ---------------------------------------------------------------------------
__global__ void __launch_bounds__(256) k_x(int N)
{
    int n = blockIdx.x * 32 + (threadIdx.x >> 3);
    int sl = threadIdx.x & 7;
    if (n >= N) return;
    int beg = g_off[n], end = g_off[n + 1];

    float4 a0 = make_float4(0, 0, 0, 0), a1 = a0, a2 = a0, a3 = a0;
    for (int i = beg + sl; i < end; i += 8) {
        float4 v = *(const float4*)&g_vbS[(size_t)i * 8];
        float4 s0, s1, s2, s3;
        sh_eval(v.x, v.y, v.z, s0, s1, s2, s3);
        a0.x += s0.x; a0.y += s0.y; a0.z += s0.z; a0.w += s0.w;
        a1.x += s1.x; a1.y += s1.y; a1.z += s1.z; a1.w += s1.w;
        a2.x += s2.x; a2.y += s2.y; a2.z += s2.z; a2.w += s2.w;
        a3.x += s3.x; a3.y += s3.y; a3.z += s3.z; a3.w += s3.w;
    }
#pragma unroll
    for (int o = 4; o > 0; o >>= 1) {
        a0.x += __shfl_down_sync(0xffffffffu, a0.x, o, 8);
        a0.y += __shfl_down_sync(0xffffffffu, a0.y, o, 8);
        a0.z += __shfl_down_sync(0xffffffffu, a0.z, o, 8);
        a0.w += __shfl_down_sync(0xffffffffu, a0.w, o, 8);
        a1.x += __shfl_down_sync(0xffffffffu, a1.x, o, 8);
        a1.y += __shfl_down_sync(0xffffffffu, a1.y, o, 8);
        a1.z += __shfl_down_sync(0xffffffffu, a1.z, o, 8);
        a1.w += __shfl_down_sync(0xffffffffu, a1.w, o, 8);
        a2.x += __shfl_down_sync(0xffffffffu, a2.x, o, 8);
        a2.y += __shfl_down_sync(0xffffffffu, a2.y, o, 8);
        a2.z += __shfl_down_sync(0xffffffffu, a2.z, o, 8);
        a2.w += __shfl_down_sync(0xffffffffu, a2.w, o, 8);
        a3.x += __shfl_down_sync(0xffffffffu, a3.x, o, 8);
        a3.y += __shfl_down_sync(0xffffffffu, a3.y, o, 8);
        a3.z += __shfl_down_sync(0xffffffffu, a3.z, o, 8);
        a3.w += __shfl_down_sync(0xffffffffu, a3.w, o, 8);
    }
    if (sl == 0) {
        float4* xp = (float4*)&g_x[(size_t)n * 16];
        xp[0] = a0; xp[1] = a1; xp[2] = a2; xp[3] = a3;
    }
}

// ---------------------------------------------------------------------------
// K5: build T with fused dots (R13 structure; vb record reads)
// ---------------------------------------------------------------------------
__global__ void __launch_bounds__(256) k_buildT(const float* __restrict__ W1a, int N)
{
    __shared__ float sW[768];
    for (int i = threadIdx.x; i < 768; i += 256) sW[i] = W1a[i];
    __syncthreads();

    int w = blockIdx.x * 8 + (threadIdx.x >> 5);
    int lane = threadIdx.x & 31;
    if (w >= N) return;
    int beg = g_off[w], end = g_off[w + 1];

    float wa0[8], wa1[8], wa2[8];
#pragma unroll
    for (int j = 0; j < 8; j++) {
        int c = j * 32 + lane;
        wa0[j] = sW[c]; wa1[j] = sW[256 + c]; wa2[j] = sW[512 + c];
    }
    float4 acc[8];
#pragma unroll
    for (int j = 0; j < 8; j++) acc[j] = make_float4(0.f, 0.f, 0.f, 0.f);

    for (int chunk = beg; chunk < end; chunk += 32) {
        int cnt = min(32, end - chunk);

        float4 dt = make_float4(0.f, 0.f, 0.f, 0.f);
        float4 bs = make_float4(0.f, 0.f, 0.f, 0.f);
        if (lane < cnt) {
            const float* rec = &g_vbS[(size_t)(chunk + lane) * 8];
            float4 v = *(const float4*)rec;
            bs = *(const float4*)(rec + 4);
            int src = __float_as_int(v.w);
            float4 s0, s1, s2, s3;
            sh_eval(v.x, v.y, v.z, s0, s1, s2, s3);
            const float4* xp = (const float4*)&g_x[(size_t)src * 16];
            float4 x0 = xp[0], x1 = xp[1], x2 = xp[2], x3 = xp[3];
            float d0 = x0.x * s0.x;
            float d1 = (x0.y * s0.y + x0.z * s0.z + x0.w * s0.w) * RS3;
            float d2 = (x1.x * s1.x + x1.y * s1.y + x1.z * s1.z +
                        x1.w * s1.w + x2.x * s2.x) * RS5;
            float d3 = (x2.y * s2.y + x2.z * s2.z + x2.w * s2.w +
                        x3.x * s3.x + x3.y * s3.y + x3.z * s3.z +
                        x3.w * s3.w) * RS7;
            dt = make_float4(d0 * INV_NN, d1 * INV_NN, d2 * INV_NN, d3 * INV_NN);
        }

        for (int j = 0; j < cnt; j++) {
            float dtx = __shfl_sync(0xffffffffu, dt.x, j);
            float dty = __shfl_sync(0xffffffffu, dt.y, j);
            float dtz = __shfl_sync(0xffffffffu, dt.z, j);
            float dtw = __shfl_sync(0xffffffffu, dt.w, j);
            float bsx = __shfl_sync(0xffffffffu, bs.x, j);
            float bsy = __shfl_sync(0xffffffffu, bs.y, j);
            float bsz = __shfl_sync(0xffffffffu, bs.z, j);
#pragma unroll
            for (int q = 0; q < 8; q++) {
                float h1 = fmaxf(fmaf(bsx, wa0[q],
                                 fmaf(bsy, wa1[q], bsz * wa2[q])), 0.f);
                acc[q].x = fmaf(h1, dtx, acc[q].x);
                acc[q].y = fmaf(h1, dty, acc[q].y);
                acc[q].z = fmaf(h1, dtz, acc[q].z);
                acc[q].w = fmaf(h1, dtw, acc[q].w);
            }
        }
    }

    uint32_t* t1 = &g_T1[(size_t)w * 512];
    uint32_t* t2 = &g_T2[(size_t)w * 512];
#pragma unroll
    for (int j = 0; j < 8; j++) {
        int idx = j * 32 + lane;
        float4 vv = acc[j];
        float hx = bf_round(vv.x), hy = bf_round(vv.y);
        float hz = bf_round(vv.z), hw = bf_round(vv.w);
        uint2 w1 = make_uint2(pack_bf2(hx, hy), pack_bf2(hz, hw));
        uint2 w2 = make_uint2(pack_bf2(vv.x - hx, vv.y - hy),
                              pack_bf2(vv.z - hz, vv.w - hw));
        *(uint2*)&t1[idx * 2] = w1;
        *(uint2*)&t2[idx * 2] = w2;
    }
}

// ---------------------------------------------------------------------------
// K6: fused GEMM1 (h) -> activation (y) -> GEMM2 (z, f32 out)  [R13 proven]
// ---------------------------------------------------------------------------
#define ASTR 20

__global__ void __launch_bounds__(128) k_gemm_fused(int M)
{
    __shared__ uint32_t A1s[64 * ASTR];
    __shared__ uint32_t A2s[64 * ASTR];
    __shared__ uint4    Bs[768];
    __shared__ uint32_t Y1[64 * 36];
    __shared__ uint32_t Y2[64 * 36];

    int tid = threadIdx.x, wid = tid >> 5, lane = tid & 31;
    int m0 = blockIdx.x * 64;

    float acc[12][4];
#pragma unroll
    for (int j = 0; j < 12; j++)
#pragma unroll
        for (int q = 0; q < 4; q++) acc[j][q] = 0.f;

    uint4 a1R[2], a2R[2], bR[6];
    const uint4 zero4 = make_uint4(0u, 0u, 0u, 0u);

#pragma unroll
    for (int it = 0; it < 2; it++) {
        int idx = tid + 128 * it;
        int r = idx >> 2, qc = idx & 3;
        int gm = m0 + r;
        if (gm < M) {
            a1R[it] = *(const uint4*)&g_T1[(size_t)gm * 512 + qc * 4];
            a2R[it] = *(const uint4*)&g_T2[(size_t)gm * 512 + qc * 4];
        } else { a1R[it] = zero4; a2R[it] = zero4; }
    }
#pragma unroll
    for (int it = 0; it < 6; it++)
        bR[it] = g_WB[tid + 128 * it];

    for (int kc = 0; kc < 32; kc++) {
        __syncthreads();
#pragma unroll
        for (int it = 0; it < 2; it++) {
            int idx = tid + 128 * it;
            int r = idx >> 2, qc = idx & 3;
            *(uint4*)&A1s[r * ASTR + qc * 4] = a1R[it];
            *(uint4*)&A2s[r * ASTR + qc * 4] = a2R[it];
        }
#pragma unroll
        for (int it = 0; it < 6; it++)
            Bs[tid + 128 * it] = bR[it];
        __syncthreads();

        if (kc < 31) {
            int kn = kc + 1;
#pragma unroll
            for (int it = 0; it < 2; it++) {
                int idx = tid + 128 * it;
                int r = idx >> 2, qc = idx & 3;
                int gm = m0 + r;
                if (gm < M) {
                    a1R[it] = *(const uint4*)&g_T1[(size_t)gm * 512 + kn * 16 + qc * 4];
                    a2R[it] = *(const uint4*)&g_T2[(size_t)gm * 512 + kn * 16 + qc * 4];
                } else { a1R[it] = zero4; a2R[it] = zero4; }
            }
#pragma unroll
            for (int it = 0; it < 6; it++)
                bR[it] = g_WB[kn * 768 + tid + 128 * it];
        }

#pragma unroll
        for (int ks = 0; ks < 2; ks++) {
            int ar = (wid * 16 + (lane >> 2)) * ASTR + ks * 8 + (lane & 3);
            uint32_t a10 = A1s[ar];
            uint32_t a11 = A1s[ar + 8 * ASTR];
            uint32_t a12 = A1s[ar + 4];
            uint32_t a13 = A1s[ar + 8 * ASTR + 4];
            uint32_t a20 = A2s[ar];
            uint32_t a21 = A2s[ar + 8 * ASTR];
            uint32_t a22 = A2s[ar + 4];
            uint32_t a23 = A2s[ar + 8 * ASTR + 4];
#pragma unroll
            for (int j = 0; j < 12; j++) {
                uint4 b = Bs[(ks * 12 + j) * 32 + lane];
                MMA_BF16(acc[j], a10, a11, a12, a13, b.x, b.y);
                MMA_BF16(acc[j], a10, a11, a12, a13, b.z, b.w);
                MMA_BF16(acc[j], a20, a21, a22, a23, b.x, b.y);
            }
        }
    }

    // ---- activation: h fragments -> y, bf16-split into Y1/Y2 smem
    int r0 = wid * 16 + (lane >> 2);
#pragma unroll
    for (int half = 0; half < 2; half++) {
        int row = r0 + half * 8;
#pragma unroll
        for (int j = 0; j < 8; j++) {
            float v0, v1;
            if (j < 4) {
                float s0 = acc[j][half * 2] * SCALE1;
                float s1 = acc[j][half * 2 + 1] * SCALE1;
                if (j < 2) { v0 = fmaxf(s0, 0.f); v1 = fmaxf(s1, 0.f); }
                else       { v0 = fabsf(s0);      v1 = fabsf(s1); }
            } else {
                float g0 = acc[j][half * 2] * SCALE1;
                float g1 = acc[j][half * 2 + 1] * SCALE1;
                float q0 = acc[j + 4][half * 2] * SCALE1;
                float q1 = acc[j + 4][half * 2 + 1] * SCALE1;
                float a0, a1;
                if ((j & 1) == 0) { a0 = fmaxf(g0, 0.f); a1 = fmaxf(g1, 0.f); }
                else              { a0 = tanhf(g0);      a1 = tanhf(g1); }
                v0 = a0 * q0; v1 = a1 * q1;
            }
            float h0 = bf_round(v0), h1 = bf_round(v1);
            int widx = row * 36 + j * 4 + (lane & 3);
            Y1[widx] = pack_bf2(h0, h1);
            Y2[widx] = pack_bf2(v0 - h0, v1 - h1);
        }
    }
    __syncthreads();

    // ---- GEMM2: z = y @ W2b^T (K=64, N=256), f32 output
#pragma unroll
    for (int nh = 0; nh < 2; nh++) {
        float zac[16][4];
#pragma unroll
        for (int j = 0; j < 16; j++)
#pragma unroll
            for (int q = 0; q < 4; q++) zac[j][q] = 0.f;

#pragma unroll
        for (int ks = 0; ks < 4; ks++) {
            int aw = (wid * 16 + (lane >> 2)) * 36 + ks * 8 + (lane & 3);
            uint32_t a10 = Y1[aw];
            uint32_t a11 = Y1[aw + 8 * 36];
            uint32_t a12 = Y1[aw + 4];
            uint32_t a13 = Y1[aw + 8 * 36 + 4];
            uint32_t a20 = Y2[aw];
            uint32_t a21 = Y2[aw + 8 * 36];
            uint32_t a22 = Y2[aw + 4];
            uint32_t a23 = Y2[aw + 8 * 36 + 4];
#pragma unroll
            for (int j = 0; j < 16; j++) {
                uint4 b = g_WB2[((nh * 16 + j) * 4 + ks) * 32 + lane];
                MMA_BF16(zac[j], a10, a11, a12, a13, b.x, b.y);
                MMA_BF16(zac[j], a10, a11, a12, a13, b.z, b.w);
                MMA_BF16(zac[j], a20, a21, a22, a23, b.x, b.y);
            }
        }
        int rr = lane >> 2, c2 = (lane & 3) * 2;
        int gm0 = m0 + wid * 16 + rr;
#pragma unroll
        for (int j = 0; j < 16; j++) {
            int col = nh * 128 + j * 8 + c2;
            if (gm0 < M)
                *(float2*)&g_z[(size_t)gm0 * 256 + col] =
                    make_float2(zac[j][0], zac[j][1]);
            if (gm0 + 8 < M)
                *(float2*)&g_z[(size_t)(gm0 + 8) * 256 + col] =
                    make_float2(zac[j][2], zac[j][3]);
        }
    }
}

// ---------------------------------------------------------------------------
// K7: final pass, warp per SRC node; z (f32) in registers; atomic to out
// ---------------------------------------------------------------------------
__global__ void __launch_bounds__(256) k_final(const float* __restrict__ W2a,
                                               float* __restrict__ out, int N)
{
    __shared__ float sW[768];
    for (int i = threadIdx.x; i < 768; i += 256) sW[i] = W2a[i];
    __syncthreads();

    int w = blockIdx.x * 8 + (threadIdx.x >> 5);
    int lane = threadIdx.x & 31;
    if (w >= N) return;
    int beg = g_off2[w], end = g_off2[w + 1];
    if (beg == end) return;

    float w0[8], w1[8], w2[8], zr[8];
    const float* zp = &g_z[(size_t)w * 256];
#pragma unroll
    for (int j = 0; j < 8; j++) {
        int c = j * 32 + lane;
        w0[j] = sW[c]; w1[j] = sW[256 + c]; w2[j] = sW[512 + c];
        zr[j] = zp[c];
    }

    for (int i = beg; i < end; i++) {
        float4 bs = *(const float4*)&g_basis2S[(size_t)i * 4];
        int dst = __float_as_int(bs.w);
        float sum = 0.f;
#pragma unroll
        for (int j = 0; j < 8; j++) {
            float h2 = fmaxf(fmaf(bs.x, w0[j], fmaf(bs.y, w1[j], bs.z * w2[j])), 0.f);
            sum = fmaf(h2, zr[j], sum);
        }
#pragma unroll
        for (int o = 16; o > 0; o >>= 1)
            sum += __shfl_down_sync(0xffffffffu, sum, o);
        if (lane == 0) atomicAdd(&out[dst], sum * SCALE2);
    }
}

// ---------------------------------------------------------------------------
// Launch
// ---------------------------------------------------------------------------
extern "C" void kernel_launch(void* const* d_in, const int* in_sizes, int n_in,
                              void* d_out, int out_size)
{
    const float* edge_vec = (const float*)d_in[0];
    const float* edge_len = (const float*)d_in[1];
    const float* W1a      = (const float*)d_in[2];
    const float* W1b      = (const float*)d_in[3];
    const float* W2a      = (const float*)d_in[4];
    const float* W2b      = (const float*)d_in[5];
    const int*   esrc     = (const int*)d_in[6];
    const int*   edst     = (const int*)d_in[7];
    float* out = (float*)d_out;

    int E = in_sizes[1];
    int N = out_size;
    if (E > EMAX) E = EMAX;
    if (N > NMAX) N = NMAX;

    int nbE = (E + 255) / 256;
    int nbScan = (N + 1023) / 1024;   // 25

    k_histR<<<nbE + 96 + 16, 256>>>(edst, esrc, E, nbE, W1b, W2b, out, N);
    k_scan <<<dim3(nbScan, 2), 1024>>>(E, N);
    k_sort <<<nbE, 256>>>(edst, esrc, edge_len, edge_vec, E, N);
    k_x    <<<(N + 31) / 32, 256>>>(N);
    k_buildT<<<(N + 7) / 8, 256>>>(W1a, N);
    k_gemm_fused<<<(N + 63) / 64, 128>>>(N);
    k_final<<<(N + 7) / 8, 256>>>(W2a, out, N);
}